// round 2
// baseline (speedup 1.0000x reference)
#include <cuda_runtime.h>
#include <cstdint>

// Problem constants (fixed by dataset): B=262144, D=32, R=16
#define R 16

// Bit layout (bit i = X[b][i]):
//   bits 0..9   -> U table (1024 entries): e_{x0}*F * M0..M8
//   bits 10..21 -> 4 mid groups of 3 bits: T_k = M_{9+3k}*M_{10+3k}*M_{11+3k}, idx in [0,8)
//   bits 22..31 -> W table (1024 entries): M21..M29 * last_{x31}
//
// Per batch:  v = U[j0];  v = v @ T_k[idx_k] (k=0..3);  out = dot(v, W[j1])
//
// Conflict-freedom: mid matrices stored with stride 260 floats (== 4 mod 32),
// so LDS.128 bank-group = 4*((idx + chunk) mod 8). idx in [0,8) -> distinct idx
// hit distinct 4-bank groups; equal idx are exact broadcasts. Zero conflicts.

// Scratch (device globals — no allocation allowed)
__device__ float g_U[1024 * 16];
__device__ float g_T[4 * 8 * 256];
__device__ float g_W[1024 * 16];

// ---------------------------------------------------------------------------
// Table builders (tiny; rebuilt every launch, deterministic)
// ---------------------------------------------------------------------------

// U[j][s] = (e_{x0} F) * M_{0,b1} * ... * M_{8,b9}, left-to-right matvecs.
__global__ void build_U(const float* __restrict__ cf, const float* __restrict__ cm) {
    int j = blockIdx.x * blockDim.x + threadIdx.x;   // 0..1023
    float v[R], nv[R];
    int x0 = j & 1;
    #pragma unroll
    for (int r = 0; r < R; r++) v[r] = cf[r * 2 + x0];          // core_first[0][r][x0]
    for (int i = 0; i < 9; i++) {
        int b = (j >> (i + 1)) & 1;
        #pragma unroll
        for (int s = 0; s < R; s++) {
            float acc = 0.f;
            #pragma unroll
            for (int r = 0; r < R; r++)
                acc += v[r] * cm[((i * R + r) * R + s) * 2 + b]; // cores_mid[i][r][s][b]
            nv[s] = acc;
        }
        #pragma unroll
        for (int s = 0; s < R; s++) v[s] = nv[s];
    }
    #pragma unroll
    for (int s = 0; s < R; s++) g_U[j * R + s] = v[s];
}

// W[j][r] = (M_{21,b0} * ... * M_{29,b8} * lastcol_{b9})[r], right-to-left matvecs.
__global__ void build_W(const float* __restrict__ cm, const float* __restrict__ cl) {
    int j = blockIdx.x * blockDim.x + threadIdx.x;   // 0..1023
    float v[R], nv[R];
    int b9 = (j >> 9) & 1;
    #pragma unroll
    for (int t = 0; t < R; t++) v[t] = cl[t * 2 + b9];          // core_last[t][0][b9]
    for (int i = 8; i >= 0; i--) {
        int c = 21 + i;
        int b = (j >> i) & 1;
        #pragma unroll
        for (int r = 0; r < R; r++) {
            float acc = 0.f;
            #pragma unroll
            for (int t = 0; t < R; t++)
                acc += cm[((c * R + r) * R + t) * 2 + b] * v[t];
            nv[r] = acc;
        }
        #pragma unroll
        for (int r = 0; r < R; r++) v[r] = nv[r];
    }
    #pragma unroll
    for (int r = 0; r < R; r++) g_W[j * R + r] = v[r];
}

// T_k[idx] = M_{9+3k,b0} * M_{10+3k,b1} * M_{11+3k,b2}.
// One thread per (idx, output col s): compute column s right-to-left.
__global__ void build_T(const float* __restrict__ cm) {
    int k   = blockIdx.x;          // 0..3
    int idx = threadIdx.x >> 4;    // 0..7
    int s   = threadIdx.x & 15;    // 0..15
    float v[R], nv[R];
    int c2 = 9 + 3 * k + 2;
    int b2 = (idx >> 2) & 1;
    #pragma unroll
    for (int t = 0; t < R; t++) v[t] = cm[((c2 * R + t) * R + s) * 2 + b2];
    for (int jj = 1; jj >= 0; jj--) {
        int c = 9 + 3 * k + jj;
        int b = (idx >> jj) & 1;
        #pragma unroll
        for (int r = 0; r < R; r++) {
            float acc = 0.f;
            #pragma unroll
            for (int t = 0; t < R; t++)
                acc += cm[((c * R + r) * R + t) * 2 + b] * v[t];
            nv[r] = acc;
        }
        #pragma unroll
        for (int r = 0; r < R; r++) v[r] = nv[r];
    }
    #pragma unroll
    for (int r = 0; r < R; r++)
        g_T[(k * 8 + idx) * 256 + r * R + s] = v[r];
}

// ---------------------------------------------------------------------------
// Main kernel.
// smem: sT[4*8*260] (matrix stride 260: 260 mod 32 == 4 -> conflict-free mids),
//       sU[1024*20], sW[1024*20] (row stride 20 keeps 16B align; idx mod 8
//       spreads bank groups for the 8 end loads/batch).
// ---------------------------------------------------------------------------
#define T_STRIDE 260
#define UW_STRIDE 20
#define ST_FLOATS (4 * 8 * T_STRIDE)            // 8320
#define SUW_FLOATS (1024 * UW_STRIDE)           // 20480
#define SMEM_FLOATS (ST_FLOATS + 2 * SUW_FLOATS)
#define SMEM_BYTES (SMEM_FLOATS * 4)            // 197120 B

extern __shared__ float sm_buf[];

__global__ __launch_bounds__(1024, 1) void tt_main(const int* __restrict__ X,
                                                   float* __restrict__ out, int B) {
    float* sT = sm_buf;
    float* sU = sm_buf + ST_FLOATS;
    float* sW = sU + SUW_FLOATS;

    for (int i = threadIdx.x; i < 4 * 8 * 256; i += 1024)
        sT[(i >> 8) * T_STRIDE + (i & 255)] = g_T[i];
    for (int i = threadIdx.x; i < 1024 * 16; i += 1024) {
        sU[(i >> 4) * UW_STRIDE + (i & 15)] = g_U[i];
        sW[(i >> 4) * UW_STRIDE + (i & 15)] = g_W[i];
    }
    __syncthreads();

    long long start = (long long)blockIdx.x * B / gridDim.x;
    long long end   = (long long)(blockIdx.x + 1) * B / gridDim.x;

    for (long long b = start + threadIdx.x; b < end; b += 1024) {
        // Build the 32-bit selector mask from this batch's X row (one 128B line).
        const int4* xr = (const int4*)(X + b * 32);
        unsigned m = 0;
        #pragma unroll
        for (int q = 0; q < 8; q++) {
            int4 x4 = xr[q];
            m |= (unsigned)(x4.x | (x4.y << 1) | (x4.z << 2) | (x4.w << 3)) << (4 * q);
        }

        // init: v = U[bits 0..9]
        const float4* u = (const float4*)(sU + (m & 1023u) * UW_STRIDE);
        float4 u0 = u[0], u1 = u[1], u2 = u[2], u3 = u[3];
        float v[16];
        v[0]=u0.x; v[1]=u0.y; v[2]=u0.z; v[3]=u0.w;
        v[4]=u1.x; v[5]=u1.y; v[6]=u1.z; v[7]=u1.w;
        v[8]=u2.x; v[9]=u2.y; v[10]=u2.z; v[11]=u2.w;
        v[12]=u3.x; v[13]=u3.y; v[14]=u3.z; v[15]=u3.w;
        unsigned mm = m >> 10;

        #pragma unroll
        for (int k = 0; k < 4; k++) {
            const float4* M = (const float4*)(sT + (k * 8 + (mm & 7u)) * T_STRIDE);
            mm >>= 3;
            float4 a0 = {0,0,0,0}, a1 = {0,0,0,0}, a2 = {0,0,0,0}, a3 = {0,0,0,0};
            #pragma unroll
            for (int r = 0; r < 16; r++) {
                float vr = v[r];
                float4 m0 = M[r * 4 + 0];
                float4 m1 = M[r * 4 + 1];
                float4 m2 = M[r * 4 + 2];
                float4 m3 = M[r * 4 + 3];
                a0.x += vr * m0.x; a0.y += vr * m0.y; a0.z += vr * m0.z; a0.w += vr * m0.w;
                a1.x += vr * m1.x; a1.y += vr * m1.y; a1.z += vr * m1.z; a1.w += vr * m1.w;
                a2.x += vr * m2.x; a2.y += vr * m2.y; a2.z += vr * m2.z; a2.w += vr * m2.w;
                a3.x += vr * m3.x; a3.y += vr * m3.y; a3.z += vr * m3.z; a3.w += vr * m3.w;
            }
            v[0]=a0.x; v[1]=a0.y; v[2]=a0.z; v[3]=a0.w;
            v[4]=a1.x; v[5]=a1.y; v[6]=a1.z; v[7]=a1.w;
            v[8]=a2.x; v[9]=a2.y; v[10]=a2.z; v[11]=a2.w;
            v[12]=a3.x; v[13]=a3.y; v[14]=a3.z; v[15]=a3.w;
        }

        // final: dot(v, W[bits 22..31])  (mm now holds bits 22..31 at 0..9)
        const float4* w = (const float4*)(sW + mm * UW_STRIDE);
        float4 w0 = w[0], w1 = w[1], w2 = w[2], w3 = w[3];
        float acc =
            v[0]*w0.x + v[1]*w0.y + v[2]*w0.z + v[3]*w0.w +
            v[4]*w1.x + v[5]*w1.y + v[6]*w1.z + v[7]*w1.w +
            v[8]*w2.x + v[9]*w2.y + v[10]*w2.z + v[11]*w2.w +
            v[12]*w3.x + v[13]*w3.y + v[14]*w3.z + v[15]*w3.w;

        out[b] = acc;
    }
}

// ---------------------------------------------------------------------------
extern "C" void kernel_launch(void* const* d_in, const int* in_sizes, int n_in,
                              void* d_out, int out_size) {
    const int*   X  = (const int*)d_in[0];
    const float* cf = (const float*)d_in[1];
    const float* cm = (const float*)d_in[2];
    const float* cl = (const float*)d_in[3];
    float* out = (float*)d_out;

    int B = in_sizes[0] / 32;   // 262144

    build_U<<<8, 128>>>(cf, cm);
    build_W<<<8, 128>>>(cm, cl);
    build_T<<<4, 128>>>(cm);

    int nsm = 148;
    cudaDeviceGetAttribute(&nsm, cudaDevAttrMultiProcessorCount, 0);

    cudaFuncSetAttribute(tt_main, cudaFuncAttributeMaxDynamicSharedMemorySize, SMEM_BYTES);
    tt_main<<<nsm, 1024, SMEM_BYTES>>>(X, out, B);
}

// round 3
// speedup vs baseline: 2.1213x; 2.1213x over previous
#include <cuda_runtime.h>
#include <cstdint>

// Problem constants (fixed by dataset): B=262144, D=32, R=16
#define R 16

// Bit layout (bit i = X[b][i]):
//   bits 0..9   -> U table (1024): e_{x0}*F * M0..M8
//   bits 10..21 -> 4 mid groups of 3 bits: T_k = M_{9+3k}*M_{10+3k}*M_{11+3k}
//   bits 22..31 -> W table (1024): M21..M29 * last_{x31}
// Per batch: v = U[j0]; v = v @ T_k[idx_k] (k=0..3); out = dot(v, W[j1])
//
// Mid matrices stored at stride 260 floats (== 4 mod 32): LDS.128 bank group
// = (idx + chunk) mod 8, injective for idx in [0,8) -> conflict-free.

__device__ float g_U[1024 * 16];
__device__ float g_T[4 * 8 * 256];
__device__ float g_W[1024 * 16];

// ---------------------------------------------------------------------------
// Warp-collaborative table builders: 16 lanes per entry, lane = vector slot,
// shfl broadcasts the carry. 144 LDG/shfl/FMA per lane instead of 2304 LDG
// per thread.
// ---------------------------------------------------------------------------

// U[j][s] = (e_{x0} F) * M_{0,b1} * ... * M_{8,b9}
__global__ void build_U(const float* __restrict__ cf, const float* __restrict__ cm) {
    int gwarp = (blockIdx.x * blockDim.x + threadIdx.x) >> 5;  // 0..511
    int lane  = threadIdx.x & 31;
    int half  = lane >> 4;
    int s     = lane & 15;
    int j     = gwarp * 2 + half;                              // 0..1023
    float v = cf[s * 2 + (j & 1)];                             // core_first[0][s][x0]
    for (int i = 0; i < 9; i++) {
        int b = (j >> (i + 1)) & 1;
        float nv = 0.f;
        #pragma unroll
        for (int r = 0; r < 16; r++) {
            float vr = __shfl_sync(0xffffffffu, v, (half << 4) + r);
            nv += vr * cm[((i * 16 + r) * 16 + s) * 2 + b];
        }
        v = nv;
    }
    g_U[j * 16 + s] = v;
}

// W[j][r] = (M_{21,b0} * ... * M_{29,b8} * lastcol_{b9})[r]
__global__ void build_W(const float* __restrict__ cm, const float* __restrict__ cl) {
    int gwarp = (blockIdx.x * blockDim.x + threadIdx.x) >> 5;
    int lane  = threadIdx.x & 31;
    int half  = lane >> 4;
    int r     = lane & 15;
    int j     = gwarp * 2 + half;
    float v = cl[r * 2 + ((j >> 9) & 1)];                      // core_last[r][0][b9]
    for (int i = 8; i >= 0; i--) {
        int c = 21 + i;
        int b = (j >> i) & 1;
        float nv = 0.f;
        #pragma unroll
        for (int t = 0; t < 16; t++) {
            float vt = __shfl_sync(0xffffffffu, v, (half << 4) + t);
            nv += cm[((c * 16 + r) * 16 + t) * 2 + b] * vt;
        }
        v = nv;
    }
    g_W[j * 16 + r] = v;
}

// T_k[idx] = M_{9+3k,b0} * M_{10+3k,b1} * M_{11+3k,b2}. Thread per (idx, col s).
__global__ void build_T(const float* __restrict__ cm) {
    int k   = blockIdx.x;          // 0..3
    int idx = threadIdx.x >> 4;    // 0..7
    int s   = threadIdx.x & 15;
    float v[R], nv[R];
    int c2 = 9 + 3 * k + 2;
    int b2 = (idx >> 2) & 1;
    #pragma unroll
    for (int t = 0; t < R; t++) v[t] = cm[((c2 * R + t) * R + s) * 2 + b2];
    for (int jj = 1; jj >= 0; jj--) {
        int c = 9 + 3 * k + jj;
        int b = (idx >> jj) & 1;
        #pragma unroll
        for (int r = 0; r < R; r++) {
            float acc = 0.f;
            #pragma unroll
            for (int t = 0; t < R; t++)
                acc += cm[((c * R + r) * R + t) * 2 + b] * v[t];
            nv[r] = acc;
        }
        #pragma unroll
        for (int r = 0; r < R; r++) v[r] = nv[r];
    }
    #pragma unroll
    for (int r = 0; r < R; r++)
        g_T[(k * 8 + idx) * 256 + r * R + s] = v[r];
}

// ---------------------------------------------------------------------------
// Main kernel. Warp processes 32 consecutive batches: coalesced ballot pack of
// X rows, then per-lane chain. Chunk-major matvec (1 float4 load per inner
// iter) lets ptxas pipeline LDS ahead of the dependent FMAs.
// ---------------------------------------------------------------------------
#define T_STRIDE 260
#define UW_STRIDE 20
#define ST_FLOATS (4 * 8 * T_STRIDE)
#define SUW_FLOATS (1024 * UW_STRIDE)
#define SMEM_FLOATS (ST_FLOATS + 2 * SUW_FLOATS)
#define SMEM_BYTES (SMEM_FLOATS * 4)

extern __shared__ float sm_buf[];

__global__ __launch_bounds__(1024, 1) void tt_main(const int* __restrict__ X,
                                                   float* __restrict__ out, int B) {
    float* sT = sm_buf;
    float* sU = sm_buf + ST_FLOATS;
    float* sW = sU + SUW_FLOATS;

    for (int i = threadIdx.x; i < 4 * 8 * 256; i += 1024)
        sT[(i >> 8) * T_STRIDE + (i & 255)] = g_T[i];
    for (int i = threadIdx.x; i < 1024 * 16; i += 1024) {
        sU[(i >> 4) * UW_STRIDE + (i & 15)] = g_U[i];
        sW[(i >> 4) * UW_STRIDE + (i & 15)] = g_W[i];
    }
    __syncthreads();

    int warp = threadIdx.x >> 5;
    int lane = threadIdx.x & 31;
    int groups = B >> 5;                       // 8192 groups of 32 batches
    int total_warps = gridDim.x << 5;          // 32 warps per block

    for (int g = (blockIdx.x << 5) + warp; g < groups; g += total_warps) {
        int base = g << 5;

        // Coalesced mask build: iteration i reads row base+i across lanes.
        unsigned mask = 0;
        #pragma unroll
        for (int i = 0; i < 32; i++) {
            int val = X[(base + i) * 32 + lane];
            unsigned bm = __ballot_sync(0xffffffffu, val);
            if (lane == i) mask = bm;
        }

        // init: v = U[bits 0..9]
        const float4* u = (const float4*)(sU + (mask & 1023u) * UW_STRIDE);
        float4 u0 = u[0], u1 = u[1], u2 = u[2], u3 = u[3];
        float v[16];
        v[0]=u0.x; v[1]=u0.y; v[2]=u0.z; v[3]=u0.w;
        v[4]=u1.x; v[5]=u1.y; v[6]=u1.z; v[7]=u1.w;
        v[8]=u2.x; v[9]=u2.y; v[10]=u2.z; v[11]=u2.w;
        v[12]=u3.x; v[13]=u3.y; v[14]=u3.z; v[15]=u3.w;
        unsigned mm = mask >> 10;

        #pragma unroll
        for (int k = 0; k < 4; k++) {
            const float4* M = (const float4*)(sT + (k * 8 + (mm & 7u)) * T_STRIDE);
            mm >>= 3;
            float nv[16];
            #pragma unroll
            for (int chunk = 0; chunk < 4; chunk++) {
                float4 a = {0.f, 0.f, 0.f, 0.f};
                #pragma unroll
                for (int r = 0; r < 16; r++) {
                    float4 mr = M[r * 4 + chunk];
                    a.x += v[r] * mr.x;
                    a.y += v[r] * mr.y;
                    a.z += v[r] * mr.z;
                    a.w += v[r] * mr.w;
                }
                nv[chunk * 4 + 0] = a.x;
                nv[chunk * 4 + 1] = a.y;
                nv[chunk * 4 + 2] = a.z;
                nv[chunk * 4 + 3] = a.w;
            }
            #pragma unroll
            for (int i = 0; i < 16; i++) v[i] = nv[i];
        }

        // final: dot(v, W[bits 22..31])
        const float4* w = (const float4*)(sW + mm * UW_STRIDE);
        float4 w0 = w[0], w1 = w[1], w2 = w[2], w3 = w[3];
        float acc =
            v[0]*w0.x + v[1]*w0.y + v[2]*w0.z + v[3]*w0.w +
            v[4]*w1.x + v[5]*w1.y + v[6]*w1.z + v[7]*w1.w +
            v[8]*w2.x + v[9]*w2.y + v[10]*w2.z + v[11]*w2.w +
            v[12]*w3.x + v[13]*w3.y + v[14]*w3.z + v[15]*w3.w;

        out[base + lane] = acc;
    }
}

// ---------------------------------------------------------------------------
extern "C" void kernel_launch(void* const* d_in, const int* in_sizes, int n_in,
                              void* d_out, int out_size) {
    const int*   X  = (const int*)d_in[0];
    const float* cf = (const float*)d_in[1];
    const float* cm = (const float*)d_in[2];
    const float* cl = (const float*)d_in[3];
    float* out = (float*)d_out;

    int B = in_sizes[0] / 32;   // 262144

    build_U<<<64, 256>>>(cf, cm);    // 512 warps, 2 entries/warp
    build_W<<<64, 256>>>(cm, cl);
    build_T<<<4, 128>>>(cm);

    int nsm = 148;
    cudaDeviceGetAttribute(&nsm, cudaDevAttrMultiProcessorCount, 0);

    cudaFuncSetAttribute(tt_main, cudaFuncAttributeMaxDynamicSharedMemorySize, SMEM_BYTES);
    tt_main<<<nsm, 1024, SMEM_BYTES>>>(X, out, B);
}

// round 4
// speedup vs baseline: 2.6447x; 1.2467x over previous
#include <cuda_runtime.h>
#include <cstdint>

// Problem constants (fixed by dataset): B=262144, D=32, R=16
#define R 16

// Bit layout (bit i = X[b][i]):
//   bits 0..9   -> U table (1024): e_{x0}*F * M0..M8
//   bits 10..21 -> 4 mid groups of 3 bits: T_k = M_{9+3k}*M_{10+3k}*M_{11+3k}
//   bits 22..31 -> W table (1024): M21..M29 * last_{x31}
// Per batch: v = U[j0]; v = v @ T_k[idx_k] (k=0..3); out = dot(v, W[j1])
//
// Mid matrices at stride 260 floats (== 4 mod 32): LDS.128 bank group =
// 4*((idx + chunk) mod 8), injective for idx in [0,8) -> conflict-free.

__device__ float g_U[1024 * 16];
__device__ float g_T[4 * 8 * 256];
__device__ float g_W[1024 * 16];

// ---------------------------------------------------------------------------
// Packed f32x2 helpers (sm_103a FFMA2 — only reachable via PTX fma.rn.f32x2)
// ---------------------------------------------------------------------------
__device__ __forceinline__ unsigned long long pack2(float a, float b) {
    unsigned long long r;
    asm("mov.b64 %0, {%1, %2};" : "=l"(r) : "f"(a), "f"(b));
    return r;
}
__device__ __forceinline__ void unpack2(unsigned long long p, float& a, float& b) {
    asm("mov.b64 {%0, %1}, %2;" : "=f"(a), "=f"(b) : "l"(p));
}
__device__ __forceinline__ unsigned long long ffma2(unsigned long long a,
                                                    unsigned long long b,
                                                    unsigned long long c) {
    unsigned long long d;
    asm("fma.rn.f32x2 %0, %1, %2, %3;" : "=l"(d) : "l"(a), "l"(b), "l"(c));
    return d;
}
__device__ __forceinline__ unsigned long long fmul2(unsigned long long a,
                                                    unsigned long long b) {
    unsigned long long d;
    asm("mul.rn.f32x2 %0, %1, %2;" : "=l"(d) : "l"(a), "l"(b));
    return d;
}
__device__ __forceinline__ unsigned long long fadd2(unsigned long long a,
                                                    unsigned long long b) {
    unsigned long long d;
    asm("add.rn.f32x2 %0, %1, %2;" : "=l"(d) : "l"(a), "l"(b));
    return d;
}

// ---------------------------------------------------------------------------
// One merged builder kernel. grid = 132 x 256 threads:
//   blocks 0..63   -> U entries (warp-collaborative, 2 entries/warp)
//   blocks 64..127 -> W entries
//   blocks 128..131 -> T group (k = bid-128), threads 0..127
// ---------------------------------------------------------------------------
__global__ void build_tables(const float* __restrict__ cf,
                             const float* __restrict__ cm,
                             const float* __restrict__ cl) {
    int bid = blockIdx.x;
    if (bid < 64) {
        // U[j][s] = (e_{x0} F) * M_{0,b1} * ... * M_{8,b9}
        int gwarp = (bid * 256 + threadIdx.x) >> 5;   // 0..511
        int lane  = threadIdx.x & 31;
        int half  = lane >> 4;
        int s     = lane & 15;
        int j     = gwarp * 2 + half;                 // 0..1023
        float v = cf[s * 2 + (j & 1)];
        for (int i = 0; i < 9; i++) {
            int b = (j >> (i + 1)) & 1;
            float nv = 0.f;
            #pragma unroll
            for (int r = 0; r < 16; r++) {
                float vr = __shfl_sync(0xffffffffu, v, (half << 4) + r);
                nv += vr * cm[((i * 16 + r) * 16 + s) * 2 + b];
            }
            v = nv;
        }
        g_U[j * 16 + s] = v;
    } else if (bid < 128) {
        // W[j][r] = (M_{21,b0} * ... * M_{29,b8} * lastcol_{b9})[r]
        int gwarp = ((bid - 64) * 256 + threadIdx.x) >> 5;
        int lane  = threadIdx.x & 31;
        int half  = lane >> 4;
        int r     = lane & 15;
        int j     = gwarp * 2 + half;
        float v = cl[r * 2 + ((j >> 9) & 1)];
        for (int i = 8; i >= 0; i--) {
            int c = 21 + i;
            int b = (j >> i) & 1;
            float nv = 0.f;
            #pragma unroll
            for (int t = 0; t < 16; t++) {
                float vt = __shfl_sync(0xffffffffu, v, (half << 4) + t);
                nv += cm[((c * 16 + r) * 16 + t) * 2 + b] * vt;
            }
            v = nv;
        }
        g_W[j * 16 + r] = v;
    } else {
        // T_k[idx] = M_{9+3k,b0} * M_{10+3k,b1} * M_{11+3k,b2}
        if (threadIdx.x >= 128) return;
        int k   = bid - 128;
        int idx = threadIdx.x >> 4;
        int s   = threadIdx.x & 15;
        float v[R], nv[R];
        int c2 = 9 + 3 * k + 2;
        int b2 = (idx >> 2) & 1;
        #pragma unroll
        for (int t = 0; t < R; t++) v[t] = cm[((c2 * R + t) * R + s) * 2 + b2];
        for (int jj = 1; jj >= 0; jj--) {
            int c = 9 + 3 * k + jj;
            int b = (idx >> jj) & 1;
            #pragma unroll
            for (int r = 0; r < R; r++) {
                float acc = 0.f;
                #pragma unroll
                for (int t = 0; t < R; t++)
                    acc += cm[((c * R + r) * R + t) * 2 + b] * v[t];
                nv[r] = acc;
            }
            #pragma unroll
            for (int r = 0; r < R; r++) v[r] = nv[r];
        }
        #pragma unroll
        for (int r = 0; r < R; r++)
            g_T[(k * 8 + idx) * 256 + r * R + s] = v[r];
    }
}

// ---------------------------------------------------------------------------
// Main kernel. Warp handles 32 consecutive batches: ballot-packed masks,
// then per-lane packed-f32x2 chain. Carry lives as 8 f32x2 pairs.
// ---------------------------------------------------------------------------
#define T_STRIDE 260
#define UW_STRIDE 20
#define ST_FLOATS (4 * 8 * T_STRIDE)
#define SUW_FLOATS (1024 * UW_STRIDE)
#define SMEM_FLOATS (ST_FLOATS + 2 * SUW_FLOATS)
#define SMEM_BYTES (SMEM_FLOATS * 4)

extern __shared__ float sm_buf[];

__global__ __launch_bounds__(1024, 1) void tt_main(const int* __restrict__ X,
                                                   float* __restrict__ out, int B) {
    float* sT = sm_buf;
    float* sU = sm_buf + ST_FLOATS;
    float* sW = sU + SUW_FLOATS;

    for (int i = threadIdx.x; i < 4 * 8 * 256; i += 1024)
        sT[(i >> 8) * T_STRIDE + (i & 255)] = g_T[i];
    for (int i = threadIdx.x; i < 1024 * 16; i += 1024) {
        sU[(i >> 4) * UW_STRIDE + (i & 15)] = g_U[i];
        sW[(i >> 4) * UW_STRIDE + (i & 15)] = g_W[i];
    }
    __syncthreads();

    int warp = threadIdx.x >> 5;
    int lane = threadIdx.x & 31;
    int groups = B >> 5;                       // 8192 groups of 32 batches
    int total_warps = gridDim.x << 5;

    for (int g = (blockIdx.x << 5) + warp; g < groups; g += total_warps) {
        int base = g << 5;

        // Coalesced mask build: iteration i reads row base+i across lanes.
        unsigned mask = 0;
        #pragma unroll
        for (int i = 0; i < 32; i++) {
            int val = X[(base + i) * 32 + lane];
            unsigned bm = __ballot_sync(0xffffffffu, val);
            if (lane == i) mask = bm;
        }

        // init: p[0..7] = U row (8 f32x2 pairs)
        unsigned long long p[8];
        {
            const ulonglong2* Up = (const ulonglong2*)(sU + (mask & 1023u) * UW_STRIDE);
            ulonglong2 a0 = Up[0], a1 = Up[1], a2 = Up[2], a3 = Up[3];
            p[0] = a0.x; p[1] = a0.y; p[2] = a1.x; p[3] = a1.y;
            p[4] = a2.x; p[5] = a2.y; p[6] = a3.x; p[7] = a3.y;
        }
        unsigned mm = mask >> 10;

        #pragma unroll
        for (int k = 0; k < 4; k++) {
            const ulonglong2* M = (const ulonglong2*)(sT + (k * 8 + (mm & 7u)) * T_STRIDE);
            mm >>= 3;
            unsigned long long acc[8];
            #pragma unroll
            for (int i = 0; i < 8; i++) {     // rows 2i and 2i+1
                float lo, hi;
                unpack2(p[i], lo, hi);
                unsigned long long bl = pack2(lo, lo);
                unsigned long long bh = pack2(hi, hi);
                ulonglong2 q0 = M[(2 * i) * 4 + 0];
                ulonglong2 q1 = M[(2 * i) * 4 + 1];
                ulonglong2 q2 = M[(2 * i) * 4 + 2];
                ulonglong2 q3 = M[(2 * i) * 4 + 3];
                if (i == 0) {
                    acc[0] = fmul2(bl, q0.x); acc[1] = fmul2(bl, q0.y);
                    acc[2] = fmul2(bl, q1.x); acc[3] = fmul2(bl, q1.y);
                    acc[4] = fmul2(bl, q2.x); acc[5] = fmul2(bl, q2.y);
                    acc[6] = fmul2(bl, q3.x); acc[7] = fmul2(bl, q3.y);
                } else {
                    acc[0] = ffma2(bl, q0.x, acc[0]); acc[1] = ffma2(bl, q0.y, acc[1]);
                    acc[2] = ffma2(bl, q1.x, acc[2]); acc[3] = ffma2(bl, q1.y, acc[3]);
                    acc[4] = ffma2(bl, q2.x, acc[4]); acc[5] = ffma2(bl, q2.y, acc[5]);
                    acc[6] = ffma2(bl, q3.x, acc[6]); acc[7] = ffma2(bl, q3.y, acc[7]);
                }
                ulonglong2 s0 = M[(2 * i + 1) * 4 + 0];
                ulonglong2 s1 = M[(2 * i + 1) * 4 + 1];
                ulonglong2 s2 = M[(2 * i + 1) * 4 + 2];
                ulonglong2 s3 = M[(2 * i + 1) * 4 + 3];
                acc[0] = ffma2(bh, s0.x, acc[0]); acc[1] = ffma2(bh, s0.y, acc[1]);
                acc[2] = ffma2(bh, s1.x, acc[2]); acc[3] = ffma2(bh, s1.y, acc[3]);
                acc[4] = ffma2(bh, s2.x, acc[4]); acc[5] = ffma2(bh, s2.y, acc[5]);
                acc[6] = ffma2(bh, s3.x, acc[6]); acc[7] = ffma2(bh, s3.y, acc[7]);
            }
            #pragma unroll
            for (int i = 0; i < 8; i++) p[i] = acc[i];
        }

        // final: dot(p, W[bits 22..31]) with two packed chains
        {
            const ulonglong2* Wp = (const ulonglong2*)(sW + mm * UW_STRIDE);
            ulonglong2 w0 = Wp[0], w1 = Wp[1], w2 = Wp[2], w3 = Wp[3];
            unsigned long long cA = fmul2(p[0], w0.x);
            unsigned long long cB = fmul2(p[1], w0.y);
            cA = ffma2(p[2], w1.x, cA);  cB = ffma2(p[3], w1.y, cB);
            cA = ffma2(p[4], w2.x, cA);  cB = ffma2(p[5], w2.y, cB);
            cA = ffma2(p[6], w3.x, cA);  cB = ffma2(p[7], w3.y, cB);
            cA = fadd2(cA, cB);
            float lo, hi;
            unpack2(cA, lo, hi);
            out[base + lane] = lo + hi;
        }
    }
}

// ---------------------------------------------------------------------------
extern "C" void kernel_launch(void* const* d_in, const int* in_sizes, int n_in,
                              void* d_out, int out_size) {
    const int*   X  = (const int*)d_in[0];
    const float* cf = (const float*)d_in[1];
    const float* cm = (const float*)d_in[2];
    const float* cl = (const float*)d_in[3];
    float* out = (float*)d_out;

    int B = in_sizes[0] / 32;   // 262144

    build_tables<<<132, 256>>>(cf, cm, cl);

    int nsm = 148;
    cudaDeviceGetAttribute(&nsm, cudaDevAttrMultiProcessorCount, 0);

    cudaFuncSetAttribute(tt_main, cudaFuncAttributeMaxDynamicSharedMemorySize, SMEM_BYTES);
    tt_main<<<nsm, 1024, SMEM_BYTES>>>(X, out, B);
}